// round 1
// baseline (speedup 1.0000x reference)
#include <cuda_runtime.h>
#include <math.h>

#define LEVELS 4
#define KCB    1024
#define DIM    64
#define NVEC   131072        // 16 * 8192
#define BLK    256
#define CHUNK  64            // codewords staged in shared per iteration

// out layout: [NVEC*DIM quantized][LEVELS*NVEC codes][1 loss]
#define QELEMS ((size_t)NVEC * DIM)

// Scratch (no device allocation allowed)
__device__ double g_mse[LEVELS];
__device__ int    g_counts[LEVELS * KCB];
__device__ float  g_c2[LEVELS * KCB];

__global__ void zero_kernel() {
    int t = blockIdx.x * blockDim.x + threadIdx.x;
    if (t < LEVELS) g_mse[t] = 0.0;
    if (t < LEVELS * KCB) g_counts[t] = 0;
}

__global__ void c2_kernel(const float* __restrict__ cb) {
    int t = blockIdx.x * blockDim.x + threadIdx.x;   // 0..4095
    if (t < LEVELS * KCB) {
        const float* v = cb + (size_t)t * DIM;
        float s = 0.f;
        #pragma unroll
        for (int d = 0; d < DIM; ++d) s += v[d] * v[d];
        g_c2[t] = s;
    }
}

__global__ __launch_bounds__(BLK, 2)
void rvq_kernel(const float* __restrict__ x,
                const float* __restrict__ cb,
                float* __restrict__ out) {
    __shared__ float  scb[CHUNK][DIM];        // 16 KB codebook chunk
    __shared__ float  sc2[CHUNK];
    __shared__ double sred[BLK / 32];

    const int n = blockIdx.x * BLK + threadIdx.x;    // one vector per thread

    // Residual lives in registers: 16 x float4 = 64 floats
    float4 r[16];
    const float4* xv = (const float4*)(x + (size_t)n * DIM);
    #pragma unroll
    for (int i = 0; i < 16; ++i) r[i] = xv[i];

    for (int l = 0; l < LEVELS; ++l) {
        const float* cbl = cb + (size_t)l * KCB * DIM;
        float best = 3.402823466e38f;
        int   bidx = 0;

        for (int c0 = 0; c0 < KCB; c0 += CHUNK) {
            __syncthreads();   // protect previous chunk's readers
            // cooperative coalesced load of CHUNK codewords + their norms
            {
                const float4* src = (const float4*)(cbl + (size_t)c0 * DIM);
                float4* dst = (float4*)&scb[0][0];
                #pragma unroll
                for (int i = threadIdx.x; i < CHUNK * DIM / 4; i += BLK)
                    dst[i] = src[i];
                if (threadIdx.x < CHUNK)
                    sc2[threadIdx.x] = g_c2[l * KCB + c0 + threadIdx.x];
            }
            __syncthreads();

            #pragma unroll 1
            for (int c = 0; c < CHUNK; ++c) {
                const float4* w = (const float4*)scb[c];   // warp-uniform -> broadcast
                float s0 = 0.f, s1 = 0.f, s2 = 0.f, s3 = 0.f;
                #pragma unroll
                for (int i = 0; i < 16; i += 4) {
                    float4 w0 = w[i], w1 = w[i + 1], w2 = w[i + 2], w3 = w[i + 3];
                    s0 += r[i].x   * w0.x + r[i].y   * w0.y + r[i].z   * w0.z + r[i].w   * w0.w;
                    s1 += r[i+1].x * w1.x + r[i+1].y * w1.y + r[i+1].z * w1.z + r[i+1].w * w1.w;
                    s2 += r[i+2].x * w2.x + r[i+2].y * w2.y + r[i+2].z * w2.z + r[i+2].w * w2.w;
                    s3 += r[i+3].x * w3.x + r[i+3].y * w3.y + r[i+3].z * w3.z + r[i+3].w * w3.w;
                }
                float s = (s0 + s1) + (s2 + s3);
                float dist = fmaf(-2.f, s, sc2[c]);
                if (dist < best) { best = dist; bidx = c0 + c; }   // first-min (ascending)
            }
        }

        atomicAdd(&g_counts[l * KCB + bidx], 1);

        // subtract chosen codeword (exact), accumulate squared residual
        const float4* q = (const float4*)(cbl + (size_t)bidx * DIM);
        float sse = 0.f;
        #pragma unroll
        for (int i = 0; i < 16; ++i) {
            float4 qv = q[i];
            r[i].x -= qv.x; r[i].y -= qv.y; r[i].z -= qv.z; r[i].w -= qv.w;
            sse += r[i].x * r[i].x + r[i].y * r[i].y
                 + r[i].z * r[i].z + r[i].w * r[i].w;
        }

        // block-reduce sse (double) -> one atomic per block per level
        double ds = (double)sse;
        #pragma unroll
        for (int o = 16; o; o >>= 1) ds += __shfl_down_sync(0xffffffffu, ds, o);
        if ((threadIdx.x & 31) == 0) sred[threadIdx.x >> 5] = ds;
        __syncthreads();
        if (threadIdx.x == 0) {
            double t = 0.0;
            #pragma unroll
            for (int w = 0; w < BLK / 32; ++w) t += sred[w];
            atomicAdd(&g_mse[l], t);
        }

        // codes: [levels, N], cast to output dtype (f32)
        out[QELEMS + (size_t)l * NVEC + n] = (float)bidx;
    }

    // quantized_out = x - final_residual
    float4* qo = (float4*)(out + (size_t)n * DIM);
    #pragma unroll
    for (int i = 0; i < 16; ++i) {
        float4 xvv = xv[i];
        float4 o4;
        o4.x = xvv.x - r[i].x; o4.y = xvv.y - r[i].y;
        o4.z = xvv.z - r[i].z; o4.w = xvv.w - r[i].w;
        qo[i] = o4;
    }
}

__global__ void finalize_kernel(float* __restrict__ out) {
    __shared__ double warpsum[8];
    const int t = threadIdx.x;     // 256 threads
    double total = 0.0;
    for (int l = 0; l < LEVELS; ++l) {
        float esum = 0.f;          // fp32 to match jax's fp32 entropy math
        for (int i = t; i < KCB; i += 256) {
            float p = (float)g_counts[l * KCB + i] / (float)NVEC;
            esum += -(p * logf(p + 1e-10f));
        }
        double e = (double)esum;
        #pragma unroll
        for (int o = 16; o; o >>= 1) e += __shfl_down_sync(0xffffffffu, e, o);
        if ((t & 31) == 0) warpsum[t >> 5] = e;
        __syncthreads();
        if (t == 0) {
            double ent = 0.0;
            #pragma unroll
            for (int w = 0; w < 8; ++w) ent += warpsum[w];
            double mse = g_mse[l] / ((double)NVEC * DIM);
            // rec_loss + com_loss = (1 + 0.25) * mean(new_residual^2)
            total += 1.25 * mse + 0.1 * ent;
        }
        __syncthreads();
    }
    if (t == 0) out[QELEMS + (size_t)LEVELS * NVEC] = (float)total;
}

extern "C" void kernel_launch(void* const* d_in, const int* in_sizes, int n_in,
                              void* d_out, int out_size) {
    const float* x  = (const float*)d_in[0];   // [16,8192,64] f32
    const float* cb = (const float*)d_in[1];   // [4,1024,64]  f32
    float* out = (float*)d_out;

    zero_kernel<<<16, 256>>>();
    c2_kernel<<<16, 256>>>(cb);
    rvq_kernel<<<NVEC / BLK, BLK>>>(x, cb, out);
    finalize_kernel<<<1, 256>>>(out);
}